// round 1
// baseline (speedup 1.0000x reference)
#include <cuda_runtime.h>
#include <cuda_bf16.h>

// Haar DWT, single level.
// Input  x: (B=16, C=64, H=256, W=256) fp32, row-major.
// Output  : (B, C*4, H/2, W/2) fp32 where channel groups of 4 are [cA, cH, cV, cD].
//
// Per 2x2 input block {a b / c d}:
//   cA = (a+b+c+d)*0.5 ; cH = (c+d-a-b)*0.5 ; cV = (b+d-a-c)*0.5 ; cD = (a-b-c+d)*0.5
//
// Each thread handles 4 adjacent output columns (8 input columns) of one output row:
//   2 rows x 2 float4 loads (128-bit), 4 float4 stores (one per sub-band plane).

static constexpr int B = 16;
static constexpr int C = 64;
static constexpr int H = 256;
static constexpr int W = 256;
static constexpr int H2 = H / 2;   // 128
static constexpr int W2 = W / 2;   // 128
static constexpr int W4 = W2 / 4;  // 32 threads per output row

__global__ __launch_bounds__(256, 8)
void dwt_haar_kernel(const float* __restrict__ x, float* __restrict__ out) {
    int idx = blockIdx.x * blockDim.x + threadIdx.x;
    // idx layout: [bc][h2][w4]
    int w4 = idx & (W4 - 1);            // 0..31
    int h2 = (idx >> 5) & (H2 - 1);     // 0..127
    int bc = idx >> 12;                 // 0..B*C-1

    // Input base for this (bc) plane
    const float* plane = x + (size_t)bc * H * W;
    int col = w4 * 8;                    // first of 8 input columns
    const float4* r0 = reinterpret_cast<const float4*>(plane + (2 * h2) * W + col);
    const float4* r1 = reinterpret_cast<const float4*>(plane + (2 * h2 + 1) * W + col);

    float4 t0 = r0[0];
    float4 t1 = r0[1];
    float4 b0 = r1[0];
    float4 b1 = r1[1];

    // pairs: (t.x,t.y),(t.z,t.w) per float4 -> 4 output columns
    float a0 = t0.x, bb0 = t0.y, c0 = b0.x, d0 = b0.y;
    float a1 = t0.z, bb1 = t0.w, c1 = b0.z, d1 = b0.w;
    float a2 = t1.x, bb2 = t1.y, c2 = b1.x, d2 = b1.y;
    float a3 = t1.z, bb3 = t1.w, c3 = b1.z, d3 = b1.w;

    float4 cA, cH, cV, cD;
    cA.x = (a0 + bb0 + c0 + d0) * 0.5f;
    cA.y = (a1 + bb1 + c1 + d1) * 0.5f;
    cA.z = (a2 + bb2 + c2 + d2) * 0.5f;
    cA.w = (a3 + bb3 + c3 + d3) * 0.5f;

    cH.x = (c0 + d0 - a0 - bb0) * 0.5f;
    cH.y = (c1 + d1 - a1 - bb1) * 0.5f;
    cH.z = (c2 + d2 - a2 - bb2) * 0.5f;
    cH.w = (c3 + d3 - a3 - bb3) * 0.5f;

    cV.x = (bb0 + d0 - a0 - c0) * 0.5f;
    cV.y = (bb1 + d1 - a1 - c1) * 0.5f;
    cV.z = (bb2 + d2 - a2 - c2) * 0.5f;
    cV.w = (bb3 + d3 - a3 - c3) * 0.5f;

    cD.x = (a0 - bb0 - c0 + d0) * 0.5f;
    cD.y = (a1 - bb1 - c1 + d1) * 0.5f;
    cD.z = (a2 - bb2 - c2 + d2) * 0.5f;
    cD.w = (a3 - bb3 - c3 + d3) * 0.5f;

    // Output: (B, C*4, H2, W2). For this bc=(b*C+c): planes bc*4 + k.
    size_t obase = ((size_t)bc * 4) * (H2 * W2) + (size_t)h2 * W2 + col / 2;
    float4* o = reinterpret_cast<float4*>(out + obase);
    constexpr size_t plane_f4 = (H2 * W2) / 4;  // stride between sub-band planes in float4 units

    float4* oA = reinterpret_cast<float4*>(out) + obase / 4;
    oA[0 * plane_f4] = cA;
    oA[1 * plane_f4] = cH;
    oA[2 * plane_f4] = cV;
    oA[3 * plane_f4] = cD;
    (void)o;
}

extern "C" void kernel_launch(void* const* d_in, const int* in_sizes, int n_in,
                              void* d_out, int out_size) {
    const float* x = (const float*)d_in[0];
    float* out = (float*)d_out;
    int total_threads = B * C * H2 * W4;          // 16*64*128*32 = 4,194,304
    int threads = 256;
    int blocks = total_threads / threads;          // 16384
    dwt_haar_kernel<<<blocks, threads>>>(x, out);
}

// round 2
// speedup vs baseline: 1.0043x; 1.0043x over previous
#include <cuda_runtime.h>
#include <cuda_bf16.h>

// Haar DWT, single level. Input (16,64,256,256) fp32 -> output (16,256,128,128).
// Each thread: 4 output columns x 2 output rows = 8 input cols x 4 input rows.
// 8 front-batched 128-bit streaming loads, 8 128-bit streaming stores.

static constexpr int B = 16;
static constexpr int C = 64;
static constexpr int H = 256;
static constexpr int W = 256;
static constexpr int H2 = H / 2;    // 128
static constexpr int W2 = W / 2;    // 128
static constexpr int W4 = W2 / 4;   // 32 threads across one output row
static constexpr int HP = H2 / 2;   // 64 row-pairs

__device__ __forceinline__ float4 ldcs4(const float4* p) { return __ldcs(p); }

__global__ __launch_bounds__(256)
void dwt_haar_kernel(const float* __restrict__ x, float* __restrict__ out) {
    int idx = blockIdx.x * blockDim.x + threadIdx.x;
    // idx layout: [bc][h2pair][w4]
    int w4 = idx & (W4 - 1);             // 0..31
    int hp = (idx >> 5) & (HP - 1);      // 0..63  (pair of output rows)
    int bc = idx >> 11;                  // 0..B*C-1

    const float* plane = x + (size_t)bc * H * W;
    int col = w4 * 8;                    // first of 8 input columns
    int r = hp * 4;                      // first of 4 input rows

    const float4* p0 = reinterpret_cast<const float4*>(plane + (size_t)(r + 0) * W + col);
    const float4* p1 = reinterpret_cast<const float4*>(plane + (size_t)(r + 1) * W + col);
    const float4* p2 = reinterpret_cast<const float4*>(plane + (size_t)(r + 2) * W + col);
    const float4* p3 = reinterpret_cast<const float4*>(plane + (size_t)(r + 3) * W + col);

    // Front-batch all 8 loads (MLP=8)
    float4 t00 = ldcs4(p0 + 0);
    float4 t01 = ldcs4(p0 + 1);
    float4 b00 = ldcs4(p1 + 0);
    float4 b01 = ldcs4(p1 + 1);
    float4 t10 = ldcs4(p2 + 0);
    float4 t11 = ldcs4(p2 + 1);
    float4 b10 = ldcs4(p3 + 0);
    float4 b11 = ldcs4(p3 + 1);

    // Output addressing: planes bc*4 + {0..3}, rows 2*hp and 2*hp+1, cols col/2..col/2+3
    constexpr size_t plane_f4 = (size_t)(H2 * W2) / 4;
    size_t obase0 = (((size_t)bc * 4) * (H2 * W2) + (size_t)(2 * hp) * W2 + col / 2) / 4;
    float4* oA0 = reinterpret_cast<float4*>(out) + obase0;
    float4* oA1 = oA0 + (W2 / 4);  // next output row

    // Row-pair 0
    {
        float4 cA, cH, cV, cD;
        float a0 = t00.x, e0 = t00.y, c0 = b00.x, d0 = b00.y;
        float a1 = t00.z, e1 = t00.w, c1 = b00.z, d1 = b00.w;
        float a2 = t01.x, e2 = t01.y, c2 = b01.x, d2 = b01.y;
        float a3 = t01.z, e3 = t01.w, c3 = b01.z, d3 = b01.w;
        cA.x = (a0 + e0 + c0 + d0) * 0.5f;  cH.x = (c0 + d0 - a0 - e0) * 0.5f;
        cV.x = (e0 + d0 - a0 - c0) * 0.5f;  cD.x = (a0 - e0 - c0 + d0) * 0.5f;
        cA.y = (a1 + e1 + c1 + d1) * 0.5f;  cH.y = (c1 + d1 - a1 - e1) * 0.5f;
        cV.y = (e1 + d1 - a1 - c1) * 0.5f;  cD.y = (a1 - e1 - c1 + d1) * 0.5f;
        cA.z = (a2 + e2 + c2 + d2) * 0.5f;  cH.z = (c2 + d2 - a2 - e2) * 0.5f;
        cV.z = (e2 + d2 - a2 - c2) * 0.5f;  cD.z = (a2 - e2 - c2 + d2) * 0.5f;
        cA.w = (a3 + e3 + c3 + d3) * 0.5f;  cH.w = (c3 + d3 - a3 - e3) * 0.5f;
        cV.w = (e3 + d3 - a3 - c3) * 0.5f;  cD.w = (a3 - e3 - c3 + d3) * 0.5f;
        __stcs(oA0 + 0 * plane_f4, cA);
        __stcs(oA0 + 1 * plane_f4, cH);
        __stcs(oA0 + 2 * plane_f4, cV);
        __stcs(oA0 + 3 * plane_f4, cD);
    }
    // Row-pair 1
    {
        float4 cA, cH, cV, cD;
        float a0 = t10.x, e0 = t10.y, c0 = b10.x, d0 = b10.y;
        float a1 = t10.z, e1 = t10.w, c1 = b10.z, d1 = b10.w;
        float a2 = t11.x, e2 = t11.y, c2 = b11.x, d2 = b11.y;
        float a3 = t11.z, e3 = t11.w, c3 = b11.z, d3 = b11.w;
        cA.x = (a0 + e0 + c0 + d0) * 0.5f;  cH.x = (c0 + d0 - a0 - e0) * 0.5f;
        cV.x = (e0 + d0 - a0 - c0) * 0.5f;  cD.x = (a0 - e0 - c0 + d0) * 0.5f;
        cA.y = (a1 + e1 + c1 + d1) * 0.5f;  cH.y = (c1 + d1 - a1 - e1) * 0.5f;
        cV.y = (e1 + d1 - a1 - c1) * 0.5f;  cD.y = (a1 - e1 - c1 + d1) * 0.5f;
        cA.z = (a2 + e2 + c2 + d2) * 0.5f;  cH.z = (c2 + d2 - a2 - e2) * 0.5f;
        cV.z = (e2 + d2 - a2 - c2) * 0.5f;  cD.z = (a2 - e2 - c2 + d2) * 0.5f;
        cA.w = (a3 + e3 + c3 + d3) * 0.5f;  cH.w = (c3 + d3 - a3 - e3) * 0.5f;
        cV.w = (e3 + d3 - a3 - c3) * 0.5f;  cD.w = (a3 - e3 - c3 + d3) * 0.5f;
        __stcs(oA1 + 0 * plane_f4, cA);
        __stcs(oA1 + 1 * plane_f4, cH);
        __stcs(oA1 + 2 * plane_f4, cV);
        __stcs(oA1 + 3 * plane_f4, cD);
    }
}

extern "C" void kernel_launch(void* const* d_in, const int* in_sizes, int n_in,
                              void* d_out, int out_size) {
    const float* x = (const float*)d_in[0];
    float* out = (float*)d_out;
    int total_threads = B * C * HP * W4;   // 16*64*64*32 = 2,097,152
    int threads = 256;
    int blocks = total_threads / threads;  // 8192
    dwt_haar_kernel<<<blocks, threads>>>(x, out);
}